// round 1
// baseline (speedup 1.0000x reference)
#include <cuda_runtime.h>
#include <cuda_bf16.h>
#include <math.h>

// Problem constants
#define BATCH   8
#define SEQ     2048
#define KDIM    1024
#define LOWD    512

// GEMM tiling
#define BM 128
#define BN 128
#define BK 8
#define TM 8
#define TN 8
#define NTHREADS 256

// ---------------------------------------------------------------------------
// Scratch (no cudaMalloc allowed): folded weights, q/k/v, attention probs
// ---------------------------------------------------------------------------
__device__ float g_Wf[3][(size_t)LOWD * KDIM];          // Wqr, Wkr, Wvr   (6 MB)
__device__ float g_q[(size_t)BATCH * SEQ * LOWD];       // 32 MB
__device__ float g_k[(size_t)BATCH * SEQ * LOWD];       // 32 MB
__device__ float g_v[(size_t)BATCH * SEQ * LOWD];       // 32 MB
__device__ float g_P[(size_t)BATCH * SEQ * SEQ];        // 134 MB

// ---------------------------------------------------------------------------
// NT GEMM: C[m][n] = alpha * sum_k A[m][k] * B[n][k]
// A: M x K row-major, B: N x K row-major, C: M x N row-major.
// Requires M%128==0, N%128==0, K%8==0 (all shapes here satisfy this).
// blockIdx.z batches via the given strides.
// ---------------------------------------------------------------------------
__global__ void __launch_bounds__(NTHREADS)
gemm_nt(const float* __restrict__ A, const float* __restrict__ B,
        float* __restrict__ C, int M, int N, int K,
        long long sA, long long sB, long long sC, float alpha)
{
    A += (long long)blockIdx.z * sA;
    B += (long long)blockIdx.z * sB;
    C += (long long)blockIdx.z * sC;

    __shared__ float As[BK][BM];
    __shared__ float Bs[BK][BN];

    const int tid = threadIdx.x;
    const int tx  = tid & 15;        // 0..15 -> col group
    const int ty  = tid >> 4;        // 0..15 -> row group
    const int m0  = blockIdx.y * BM;
    const int n0  = blockIdx.x * BN;

    const int lr = tid >> 1;         // 0..127 row within tile
    const int lk = (tid & 1) * 4;    // 0 or 4

    float acc[TM][TN];
    #pragma unroll
    for (int i = 0; i < TM; i++)
        #pragma unroll
        for (int j = 0; j < TN; j++) acc[i][j] = 0.0f;

    for (int k0 = 0; k0 < K; k0 += BK) {
        float4 a = *(const float4*)(A + (size_t)(m0 + lr) * K + k0 + lk);
        float4 b = *(const float4*)(B + (size_t)(n0 + lr) * K + k0 + lk);
        As[lk + 0][lr] = a.x; As[lk + 1][lr] = a.y;
        As[lk + 2][lr] = a.z; As[lk + 3][lr] = a.w;
        Bs[lk + 0][lr] = b.x; Bs[lk + 1][lr] = b.y;
        Bs[lk + 2][lr] = b.z; Bs[lk + 3][lr] = b.w;
        __syncthreads();

        #pragma unroll
        for (int kk = 0; kk < BK; kk++) {
            float4 a0 = *(const float4*)&As[kk][ty * TM];
            float4 a1 = *(const float4*)&As[kk][ty * TM + 4];
            float4 b0 = *(const float4*)&Bs[kk][tx * TN];
            float4 b1 = *(const float4*)&Bs[kk][tx * TN + 4];
            float ar[TM] = {a0.x, a0.y, a0.z, a0.w, a1.x, a1.y, a1.z, a1.w};
            float br[TN] = {b0.x, b0.y, b0.z, b0.w, b1.x, b1.y, b1.z, b1.w};
            #pragma unroll
            for (int i = 0; i < TM; i++)
                #pragma unroll
                for (int j = 0; j < TN; j++)
                    acc[i][j] = fmaf(ar[i], br[j], acc[i][j]);
        }
        __syncthreads();
    }

    #pragma unroll
    for (int i = 0; i < TM; i++) {
        #pragma unroll
        for (int j = 0; j < TN; j += 4) {
            float4 v;
            v.x = acc[i][j + 0] * alpha;
            v.y = acc[i][j + 1] * alpha;
            v.z = acc[i][j + 2] * alpha;
            v.w = acc[i][j + 3] * alpha;
            *(float4*)(C + (size_t)(m0 + ty * TM + i) * N + n0 + tx * TN + j) = v;
        }
    }
}

// ---------------------------------------------------------------------------
// NN GEMM: C[m][n] = alpha * sum_k A[m][k] * B[k][n]
// A: M x K row-major, B: K x N row-major.
// Requires M%128==0, N%128==0, K%8==0.
// ---------------------------------------------------------------------------
__global__ void __launch_bounds__(NTHREADS)
gemm_nn(const float* __restrict__ A, const float* __restrict__ B,
        float* __restrict__ C, int M, int N, int K,
        long long sA, long long sB, long long sC, float alpha)
{
    A += (long long)blockIdx.z * sA;
    B += (long long)blockIdx.z * sB;
    C += (long long)blockIdx.z * sC;

    __shared__ float As[BK][BM];
    __shared__ float Bs[BK][BN];

    const int tid = threadIdx.x;
    const int tx  = tid & 15;
    const int ty  = tid >> 4;
    const int m0  = blockIdx.y * BM;
    const int n0  = blockIdx.x * BN;

    const int lr  = tid >> 1;        // A row 0..127
    const int lk  = (tid & 1) * 4;   // A k 0 or 4
    const int bk  = tid >> 5;        // B k row 0..7
    const int bn4 = (tid & 31) * 4;  // B col 0..124

    float acc[TM][TN];
    #pragma unroll
    for (int i = 0; i < TM; i++)
        #pragma unroll
        for (int j = 0; j < TN; j++) acc[i][j] = 0.0f;

    for (int k0 = 0; k0 < K; k0 += BK) {
        float4 a = *(const float4*)(A + (size_t)(m0 + lr) * K + k0 + lk);
        float4 b = *(const float4*)(B + (size_t)(k0 + bk) * N + n0 + bn4);
        As[lk + 0][lr] = a.x; As[lk + 1][lr] = a.y;
        As[lk + 2][lr] = a.z; As[lk + 3][lr] = a.w;
        *(float4*)&Bs[bk][bn4] = b;
        __syncthreads();

        #pragma unroll
        for (int kk = 0; kk < BK; kk++) {
            float4 a0 = *(const float4*)&As[kk][ty * TM];
            float4 a1 = *(const float4*)&As[kk][ty * TM + 4];
            float4 b0 = *(const float4*)&Bs[kk][tx * TN];
            float4 b1 = *(const float4*)&Bs[kk][tx * TN + 4];
            float ar[TM] = {a0.x, a0.y, a0.z, a0.w, a1.x, a1.y, a1.z, a1.w};
            float br[TN] = {b0.x, b0.y, b0.z, b0.w, b1.x, b1.y, b1.z, b1.w};
            #pragma unroll
            for (int i = 0; i < TM; i++)
                #pragma unroll
                for (int j = 0; j < TN; j++)
                    acc[i][j] = fmaf(ar[i], br[j], acc[i][j]);
        }
        __syncthreads();
    }

    #pragma unroll
    for (int i = 0; i < TM; i++) {
        #pragma unroll
        for (int j = 0; j < TN; j += 4) {
            float4 v;
            v.x = acc[i][j + 0] * alpha;
            v.y = acc[i][j + 1] * alpha;
            v.z = acc[i][j + 2] * alpha;
            v.w = acc[i][j + 3] * alpha;
            *(float4*)(C + (size_t)(m0 + ty * TM + i) * N + n0 + tx * TN + j) = v;
        }
    }
}

// ---------------------------------------------------------------------------
// Row softmax, one block (256 threads) per row of `ncols` floats, in place.
// ---------------------------------------------------------------------------
__global__ void __launch_bounds__(256)
softmax_rows(float* __restrict__ P, int ncols)
{
    float* row = P + (size_t)blockIdx.x * ncols;
    __shared__ float red[256];
    const int tid = threadIdx.x;

    float m = -INFINITY;
    for (int j = tid; j < ncols; j += 256) m = fmaxf(m, row[j]);
    red[tid] = m;
    __syncthreads();
    #pragma unroll
    for (int s = 128; s > 0; s >>= 1) {
        if (tid < s) red[tid] = fmaxf(red[tid], red[tid + s]);
        __syncthreads();
    }
    m = red[0];
    __syncthreads();

    float sum = 0.0f;
    for (int j = tid; j < ncols; j += 256) {
        float e = __expf(row[j] - m);
        row[j] = e;
        sum += e;
    }
    red[tid] = sum;
    __syncthreads();
    #pragma unroll
    for (int s = 128; s > 0; s >>= 1) {
        if (tid < s) red[tid] += red[tid + s];
        __syncthreads();
    }
    const float inv = 1.0f / red[0];
    for (int j = tid; j < ncols; j += 256) row[j] *= inv;
}

// ---------------------------------------------------------------------------
// Launch sequence (graph-capturable; no sync, no alloc)
// ---------------------------------------------------------------------------
extern "C" void kernel_launch(void* const* d_in, const int* in_sizes, int n_in,
                              void* d_out, int out_size)
{
    const float* Q  = (const float*)d_in[0];
    const float* K  = (const float*)d_in[1];
    const float* V  = (const float*)d_in[2];
    const float* Wr = (const float*)d_in[3];
    const float* Wq = (const float*)d_in[4];
    const float* Wk = (const float*)d_in[5];
    const float* Wv = (const float*)d_in[6];
    float* out = (float*)d_out;

    float *pWf, *pq, *pk, *pv, *pP;
    cudaGetSymbolAddress((void**)&pWf, g_Wf);
    cudaGetSymbolAddress((void**)&pq,  g_q);
    cudaGetSymbolAddress((void**)&pk,  g_k);
    cudaGetSymbolAddress((void**)&pv,  g_v);
    cudaGetSymbolAddress((void**)&pP,  g_P);
    float* Wf0 = pWf;
    float* Wf1 = pWf + (size_t)LOWD * KDIM;
    float* Wf2 = pWf + 2 * (size_t)LOWD * KDIM;

    const int MQ = BATCH * SEQ;            // 16384 rows of Q/K/V
    const float scale = 1.0f / sqrtf((float)LOWD);

    // 1) Fold weights: Wf = Wx @ Wr   (M=512, N=1024, K=512), NN
    {
        dim3 grid(KDIM / BN, LOWD / BM, 1);
        gemm_nn<<<grid, NTHREADS>>>(Wq, Wr, Wf0, LOWD, KDIM, LOWD, 0, 0, 0, 1.0f);
        gemm_nn<<<grid, NTHREADS>>>(Wk, Wr, Wf1, LOWD, KDIM, LOWD, 0, 0, 0, 1.0f);
        gemm_nn<<<grid, NTHREADS>>>(Wv, Wr, Wf2, LOWD, KDIM, LOWD, 0, 0, 0, 1.0f);
    }

    // 2) Projections: q = Q @ Wf0^T  (M=16384, N=512, K=1024), NT
    {
        dim3 grid(LOWD / BN, MQ / BM, 1);
        gemm_nt<<<grid, NTHREADS>>>(Q, Wf0, pq, MQ, LOWD, KDIM, 0, 0, 0, 1.0f);
        gemm_nt<<<grid, NTHREADS>>>(K, Wf1, pk, MQ, LOWD, KDIM, 0, 0, 0, 1.0f);
        gemm_nt<<<grid, NTHREADS>>>(V, Wf2, pv, MQ, LOWD, KDIM, 0, 0, 0, 1.0f);
    }

    // 3) Scores: P[b] = scale * q[b] @ k[b]^T  (M=N=2048, K=512), batched NT
    {
        dim3 grid(SEQ / BN, SEQ / BM, BATCH);
        gemm_nt<<<grid, NTHREADS>>>(pq, pk, pP, SEQ, SEQ, LOWD,
                                    (long long)SEQ * LOWD,
                                    (long long)SEQ * LOWD,
                                    (long long)SEQ * SEQ, scale);
    }

    // 4) Softmax over last dim of P: 16384 rows of 2048
    softmax_rows<<<BATCH * SEQ, 256>>>(pP, SEQ);

    // 5) Output: out[b] = P[b] @ v[b]  (M=2048, N=512, K=2048), batched NN
    {
        dim3 grid(LOWD / BN, SEQ / BM, BATCH);
        gemm_nn<<<grid, NTHREADS>>>(pP, pv, out, SEQ, LOWD, SEQ,
                                    (long long)SEQ * SEQ,
                                    (long long)SEQ * LOWD,
                                    (long long)SEQ * LOWD, 1.0f);
    }
}

// round 2
// speedup vs baseline: 2.7322x; 2.7322x over previous
#include <cuda_runtime.h>
#include <math.h>
#include <stdint.h>

#define BATCH 8
#define SEQ   2048
#define KDIM  1024
#define LOWD  512

#define BM 128
#define BN 128
#define BK 16
#define BKP 20          // padded k-stride (conflict-free fragment LDS)

// ---------------------------------------------------------------------------
// Scratch (no cudaMalloc allowed)
// ---------------------------------------------------------------------------
__device__ __align__(256) float g_Wf[3][(size_t)LOWD * KDIM];     // folded weights (tf32-rounded)
__device__ __align__(256) float g_q[(size_t)BATCH * SEQ * LOWD];  // tf32-rounded
__device__ __align__(256) float g_k[(size_t)BATCH * SEQ * LOWD];
__device__ __align__(256) float g_v[(size_t)BATCH * SEQ * LOWD];
__device__ __align__(256) float g_P[(size_t)BATCH * SEQ * SEQ];   // scores / probs

// ---------------------------------------------------------------------------
// Helpers
// ---------------------------------------------------------------------------
__device__ __forceinline__ uint32_t tf32b(float x) {
    uint32_t u; asm("cvt.rna.tf32.f32 %0, %1;" : "=r"(u) : "f"(x)); return u;
}
__device__ __forceinline__ float tf32r(float x) {
    return __uint_as_float(tf32b(x));
}
__device__ __forceinline__ void cp16(void* s, const void* g) {
    unsigned sa = (unsigned)__cvta_generic_to_shared(s);
    asm volatile("cp.async.cg.shared.global [%0], [%1], 16;\n" :: "r"(sa), "l"(g));
}
__device__ __forceinline__ void cp_commit() { asm volatile("cp.async.commit_group;\n"); }
template<int NW> __device__ __forceinline__ void cp_wait() {
    asm volatile("cp.async.wait_group %0;\n" :: "n"(NW));
}
__device__ __forceinline__ void mma_tf32(float* c, const uint32_t* a, const uint32_t* b) {
    asm volatile(
        "mma.sync.aligned.m16n8k8.row.col.f32.tf32.tf32.f32 "
        "{%0,%1,%2,%3}, {%4,%5,%6,%7}, {%8,%9}, {%0,%1,%2,%3};\n"
        : "+f"(c[0]), "+f"(c[1]), "+f"(c[2]), "+f"(c[3])
        : "r"(a[0]), "r"(a[1]), "r"(a[2]), "r"(a[3]), "r"(b[0]), "r"(b[1]));
}

// ---------------------------------------------------------------------------
// Tensor-core tf32 GEMM.
//   TRANSB=true : C = alpha * A[M,K] * B[N,K]^T      (NT)
//   TRANSB=false: C = alpha * A[M,K] * B[K,N]        (NN)
// CVTA/CVTB: apply cvt.rna to A/B fragments (for raw fp32 operands).
// ROUND: rna-round outputs to tf32-representable fp32.
// Requires M%128==0, N%128==0, K%16==0. blockIdx.z batches via strides.
// ---------------------------------------------------------------------------
template<bool TRANSB, bool CVTA, bool CVTB, bool ROUND>
__global__ void __launch_bounds__(256)
tgemm(const float* __restrict__ A, const float* __restrict__ B,
      float* __restrict__ C, int K, int ldA, int ldB, int ldC,
      long long sA, long long sB, long long sC, float alpha)
{
    __shared__ float As[2][BM][BKP];   // m-major, padded
    __shared__ float Bs[2][BN][BKP];   // n-major, padded

    A += (long long)blockIdx.z * sA;
    B += (long long)blockIdx.z * sB;
    C += (long long)blockIdx.z * sC;

    const int tid  = threadIdx.x;
    const int lane = tid & 31;
    const int warp = tid >> 5;
    const int wm   = (warp & 3) * 32;   // 4 warps along M
    const int wn   = (warp >> 2) * 64;  // 2 warps along N
    const int m0   = blockIdx.y * BM;
    const int n0   = blockIdx.x * BN;

    // A / NT-B tile loader mapping: 256 threads, 8 floats each
    const int lr = tid >> 1;            // 0..127 row within tile
    const int lk = (tid & 1) * 8;       // 0 or 8
    // NN-B loader mapping
    const int bn  = tid & 127;
    const int bk0 = (tid >> 7) * 8;

    float acc[2][8][4];
    #pragma unroll
    for (int i = 0; i < 2; i++)
        #pragma unroll
        for (int j = 0; j < 8; j++)
            #pragma unroll
            for (int l = 0; l < 4; l++) acc[i][j][l] = 0.0f;

    const int KT = K / BK;
    float regB[8];

    // ---- prologue: tile 0 ----
    {
        const float* Ag = A + (size_t)(m0 + lr) * ldA + lk;
        cp16(&As[0][lr][lk],     Ag);
        cp16(&As[0][lr][lk + 4], Ag + 4);
        if (TRANSB) {
            const float* Bg = B + (size_t)(n0 + lr) * ldB + lk;
            cp16(&Bs[0][lr][lk],     Bg);
            cp16(&Bs[0][lr][lk + 4], Bg + 4);
        } else {
            #pragma unroll
            for (int j = 0; j < 8; j++)
                regB[j] = B[(size_t)(bk0 + j) * ldB + n0 + bn];
        }
        cp_commit();
    }

    for (int kt = 0; kt < KT; kt++) {
        const int buf = kt & 1;

        if (!TRANSB) {   // stage current B tile from regs
            #pragma unroll
            for (int j = 0; j < 8; j++) Bs[buf][bn][bk0 + j] = regB[j];
        }
        if (kt + 1 < KT) {
            const int nb = (kt + 1) & 1;
            const int k0 = (kt + 1) * BK;
            const float* Ag = A + (size_t)(m0 + lr) * ldA + k0 + lk;
            cp16(&As[nb][lr][lk],     Ag);
            cp16(&As[nb][lr][lk + 4], Ag + 4);
            if (TRANSB) {
                const float* Bg = B + (size_t)(n0 + lr) * ldB + k0 + lk;
                cp16(&Bs[nb][lr][lk],     Bg);
                cp16(&Bs[nb][lr][lk + 4], Bg + 4);
            } else {
                #pragma unroll
                for (int j = 0; j < 8; j++)
                    regB[j] = B[(size_t)(k0 + bk0 + j) * ldB + n0 + bn];
            }
            cp_commit();
            cp_wait<1>();
        } else {
            cp_wait<0>();
        }
        __syncthreads();

        const int g  = lane >> 2;
        const int tg = lane & 3;
        #pragma unroll
        for (int ks = 0; ks < 2; ks++) {
            const int kk = ks * 8;
            uint32_t a[2][4];
            #pragma unroll
            for (int mi = 0; mi < 2; mi++) {
                const int r = wm + mi * 16 + g;
                float f0 = As[buf][r    ][kk + tg];
                float f1 = As[buf][r + 8][kk + tg];
                float f2 = As[buf][r    ][kk + tg + 4];
                float f3 = As[buf][r + 8][kk + tg + 4];
                if (CVTA) {
                    a[mi][0] = tf32b(f0); a[mi][1] = tf32b(f1);
                    a[mi][2] = tf32b(f2); a[mi][3] = tf32b(f3);
                } else {
                    a[mi][0] = __float_as_uint(f0); a[mi][1] = __float_as_uint(f1);
                    a[mi][2] = __float_as_uint(f2); a[mi][3] = __float_as_uint(f3);
                }
            }
            #pragma unroll
            for (int ni = 0; ni < 8; ni++) {
                const int n = wn + ni * 8 + g;
                float fb0 = Bs[buf][n][kk + tg];
                float fb1 = Bs[buf][n][kk + tg + 4];
                uint32_t b[2];
                if (CVTB) { b[0] = tf32b(fb0); b[1] = tf32b(fb1); }
                else      { b[0] = __float_as_uint(fb0); b[1] = __float_as_uint(fb1); }
                mma_tf32(acc[0][ni], a[0], b);
                mma_tf32(acc[1][ni], a[1], b);
            }
        }
        __syncthreads();
    }

    // ---- epilogue ----
    const int g  = lane >> 2;
    const int tg = lane & 3;
    #pragma unroll
    for (int mi = 0; mi < 2; mi++) {
        #pragma unroll
        for (int ni = 0; ni < 8; ni++) {
            const int r = m0 + wm + mi * 16 + g;
            const int c = n0 + wn + ni * 8 + tg * 2;
            float v0 = acc[mi][ni][0] * alpha, v1 = acc[mi][ni][1] * alpha;
            float v2 = acc[mi][ni][2] * alpha, v3 = acc[mi][ni][3] * alpha;
            if (ROUND) { v0 = tf32r(v0); v1 = tf32r(v1); v2 = tf32r(v2); v3 = tf32r(v3); }
            *(float2*)(C + (size_t)r * ldC + c)       = make_float2(v0, v1);
            *(float2*)(C + (size_t)(r + 8) * ldC + c) = make_float2(v2, v3);
        }
    }
}

// ---------------------------------------------------------------------------
// Row softmax (in place), rna-rounds output so it is a clean tf32 A operand.
// ---------------------------------------------------------------------------
__global__ void __launch_bounds__(256)
softmax_rows(float* __restrict__ P, int ncols)
{
    float* row = P + (size_t)blockIdx.x * ncols;
    __shared__ float red[256];
    const int tid = threadIdx.x;

    float m = -INFINITY;
    for (int j = tid; j < ncols; j += 256) m = fmaxf(m, row[j]);
    red[tid] = m;
    __syncthreads();
    #pragma unroll
    for (int s = 128; s > 0; s >>= 1) {
        if (tid < s) red[tid] = fmaxf(red[tid], red[tid + s]);
        __syncthreads();
    }
    m = red[0];
    __syncthreads();

    float sum = 0.0f;
    for (int j = tid; j < ncols; j += 256) {
        float e = __expf(row[j] - m);
        row[j] = e;
        sum += e;
    }
    red[tid] = sum;
    __syncthreads();
    #pragma unroll
    for (int s = 128; s > 0; s >>= 1) {
        if (tid < s) red[tid] += red[tid + s];
        __syncthreads();
    }
    const float inv = 1.0f / red[0];
    for (int j = tid; j < ncols; j += 256) row[j] = tf32r(row[j] * inv);
}

// ---------------------------------------------------------------------------
// Launch sequence (graph-capturable; no sync, no alloc)
// ---------------------------------------------------------------------------
extern "C" void kernel_launch(void* const* d_in, const int* in_sizes, int n_in,
                              void* d_out, int out_size)
{
    const float* Q  = (const float*)d_in[0];
    const float* K  = (const float*)d_in[1];
    const float* V  = (const float*)d_in[2];
    const float* Wr = (const float*)d_in[3];
    const float* Wq = (const float*)d_in[4];
    const float* Wk = (const float*)d_in[5];
    const float* Wv = (const float*)d_in[6];
    float* out = (float*)d_out;

    float *pWf, *pq, *pk, *pv, *pP;
    cudaGetSymbolAddress((void**)&pWf, g_Wf);
    cudaGetSymbolAddress((void**)&pq,  g_q);
    cudaGetSymbolAddress((void**)&pk,  g_k);
    cudaGetSymbolAddress((void**)&pv,  g_v);
    cudaGetSymbolAddress((void**)&pP,  g_P);
    float* Wf0 = pWf;
    float* Wf1 = pWf + (size_t)LOWD * KDIM;
    float* Wf2 = pWf + 2 * (size_t)LOWD * KDIM;

    const float scale = 1.0f / sqrtf((float)LOWD);
    dim3 blk(256);

    // 1) Fold weights on tensor cores: Wf = Wq @ Wr (NN, M=512,N=1024,K=512)
    //    Raw fp32 operands -> CVTA+CVTB; output rna-rounded.
    {
        dim3 grid(KDIM / BN, LOWD / BM, 1);
        tgemm<false, true, true, true><<<grid, blk>>>(Wq, Wr, Wf0, LOWD, LOWD, KDIM, KDIM, 0, 0, 0, 1.0f);
        tgemm<false, true, true, true><<<grid, blk>>>(Wk, Wr, Wf1, LOWD, LOWD, KDIM, KDIM, 0, 0, 0, 1.0f);
        tgemm<false, true, true, true><<<grid, blk>>>(Wv, Wr, Wf2, LOWD, LOWD, KDIM, KDIM, 0, 0, 0, 1.0f);
    }

    // 2) Projections: q = Q @ Wf^T (NT, M=16384,N=512,K=1024)
    //    A raw -> CVTA; B pre-rounded; output rounded.
    {
        dim3 grid(LOWD / BN, (BATCH * SEQ) / BM, 1);
        tgemm<true, true, false, true><<<grid, blk>>>(Q, Wf0, pq, KDIM, KDIM, KDIM, LOWD, 0, 0, 0, 1.0f);
        tgemm<true, true, false, true><<<grid, blk>>>(K, Wf1, pk, KDIM, KDIM, KDIM, LOWD, 0, 0, 0, 1.0f);
        tgemm<true, true, false, true><<<grid, blk>>>(V, Wf2, pv, KDIM, KDIM, KDIM, LOWD, 0, 0, 0, 1.0f);
    }

    // 3) Scores: P[b] = scale * q[b] @ k[b]^T (NT batched, M=N=2048,K=512)
    {
        dim3 grid(SEQ / BN, SEQ / BM, BATCH);
        tgemm<true, false, false, false><<<grid, blk>>>(
            pq, pk, pP, LOWD, LOWD, LOWD, SEQ,
            (long long)SEQ * LOWD, (long long)SEQ * LOWD, (long long)SEQ * SEQ, scale);
    }

    // 4) Softmax over rows of P (16384 rows x 2048), rna-rounded output
    softmax_rows<<<BATCH * SEQ, blk>>>(pP, SEQ);

    // 5) Output: out[b] = P[b] @ v[b] (NN batched, M=2048,N=512,K=2048)
    {
        dim3 grid(LOWD / BN, SEQ / BM, BATCH);
        tgemm<false, false, false, false><<<grid, blk>>>(
            pP, pv, out, SEQ, SEQ, LOWD, LOWD,
            (long long)SEQ * SEQ, (long long)SEQ * LOWD, (long long)SEQ * LOWD, 1.0f);
    }
}

// round 5
// speedup vs baseline: 4.6795x; 1.7127x over previous
#include <cuda_runtime.h>
#include <cuda_fp16.h>
#include <math.h>
#include <stdint.h>

#define BATCH 8
#define SEQ   2048
#define KDIM  1024
#define LOWD  512

// ---------------------------------------------------------------------------
// Scratch (no cudaMalloc allowed)
// ---------------------------------------------------------------------------
__device__ __align__(1024) __half g_Wf [3 * (size_t)LOWD * KDIM];     // folded weights (fp16)
__device__ __align__(1024) __half g_qkv[3 * (size_t)BATCH * SEQ * LOWD]; // q,k,v (fp16)
__device__ __align__(1024) __half g_vT [(size_t)BATCH * SEQ * LOWD];  // v transposed (fp16)
__device__ __align__(1024) float  g_P  [(size_t)BATCH * SEQ * SEQ];   // raw scores (fp32)
__device__ __align__(1024) __half g_Ph [(size_t)BATCH * SEQ * SEQ];   // softmax probs (fp16)

// ---------------------------------------------------------------------------
// Helpers
// ---------------------------------------------------------------------------
__device__ __forceinline__ uint32_t tf32b(float x) {
    uint32_t u; asm("cvt.rna.tf32.f32 %0, %1;" : "=r"(u) : "f"(x)); return u;
}
__device__ __forceinline__ uint32_t smem_u32(const void* p) {
    uint32_t a;
    asm("{ .reg .u64 t; cvta.to.shared.u64 t, %1; cvt.u32.u64 %0, t; }" : "=r"(a) : "l"(p));
    return a;
}
__device__ __forceinline__ uint32_t f2h2(float lo, float hi) {
    __half2 h = __floats2half2_rn(lo, hi);
    return *(uint32_t*)&h;
}
__device__ __forceinline__ void ldsm_x4(uint32_t* r, uint32_t addr) {
    asm volatile("ldmatrix.sync.aligned.m8n8.x4.shared.b16 {%0,%1,%2,%3}, [%4];"
        : "=r"(r[0]), "=r"(r[1]), "=r"(r[2]), "=r"(r[3]) : "r"(addr));
}
__device__ __forceinline__ void mma_f16(float* c, const uint32_t* a, uint32_t b0, uint32_t b1) {
    asm volatile(
        "mma.sync.aligned.m16n8k16.row.col.f32.f16.f16.f32 "
        "{%0,%1,%2,%3}, {%4,%5,%6,%7}, {%8,%9}, {%0,%1,%2,%3};"
        : "+f"(c[0]), "+f"(c[1]), "+f"(c[2]), "+f"(c[3])
        : "r"(a[0]), "r"(a[1]), "r"(a[2]), "r"(a[3]), "r"(b0), "r"(b1));
}

// ---------------------------------------------------------------------------
// fp16-operand NT GEMM: C[m][n] = alpha * sum_k A[m][k] * B[n][k]
// BM=BN=128, BK=32. 8 warps (4x2), warp tile 32x64. ldmatrix + XOR swizzle.
// CVTA: A is fp32 in gmem, converted (rn) to fp16 while staging.
// OUTH: write C as fp16, else fp32.
// A pointer chosen from {A0,A1,A2} by blockIdx.z (fused triple launches);
// for batched calls pass the same pointer 3x and use sA.
// Requires M%128==0, N%128==0, K%32==0.
// ---------------------------------------------------------------------------
template<bool CVTA, bool OUTH>
__global__ void __launch_bounds__(256, 2)
hgemm_nt(const void* A0_, const void* A1_, const void* A2_,
         const __half* __restrict__ B_, void* C_,
         int K, int ldA, int ldB, int ldC,
         long long sA, long long sB, long long sC, float alpha)
{
    __shared__ __align__(16) __half As[2][128 * 32];
    __shared__ __align__(16) __half Bs[2][128 * 32];

    const int z = blockIdx.z;
    const void* Asel = (z == 1) ? A1_ : ((z == 2) ? A2_ : A0_);
    const float*  Af = CVTA ? ((const float*)Asel + (size_t)z * sA) : nullptr;
    const __half* Ah = CVTA ? nullptr : ((const __half*)Asel + (size_t)z * sA);
    const __half* Bp = B_ + (size_t)z * sB;
    float*  Cf = OUTH ? nullptr : ((float*)C_ + (size_t)z * sC);
    __half* Ch = OUTH ? ((__half*)C_ + (size_t)z * sC) : nullptr;

    const int tid  = threadIdx.x;
    const int lane = tid & 31;
    const int warp = tid >> 5;
    const int wm   = (warp & 3) * 32;
    const int wn   = (warp >> 2) * 64;
    const int m0   = blockIdx.y * 128;
    const int n0   = blockIdx.x * 128;

    // staging mapping: each thread owns one row-half (16 halfs = 2 chunks of 8)
    const int srow = tid >> 1;
    const int cc   = (tid & 1) * 2;          // chunk base (0 or 2)
    const int ssw  = (srow >> 1) & 3;        // XOR swizzle for this row

    float acc[2][8][4];
    #pragma unroll
    for (int i = 0; i < 2; i++)
        #pragma unroll
        for (int j = 0; j < 8; j++)
            #pragma unroll
            for (int l = 0; l < 4; l++) acc[i][j][l] = 0.0f;

    const uint32_t As_u = smem_u32(As);
    const uint32_t Bs_u = smem_u32(Bs);
    const int KT = K / 32;

    auto loadA = [&](int k0, uint4& c0, uint4& c1) {
        if (CVTA) {
            const float* p = Af + (size_t)(m0 + srow) * ldA + k0 + cc * 8;
            float4 f0 = *(const float4*)(p);
            float4 f1 = *(const float4*)(p + 4);
            float4 f2 = *(const float4*)(p + 8);
            float4 f3 = *(const float4*)(p + 12);
            c0 = make_uint4(f2h2(f0.x, f0.y), f2h2(f0.z, f0.w), f2h2(f1.x, f1.y), f2h2(f1.z, f1.w));
            c1 = make_uint4(f2h2(f2.x, f2.y), f2h2(f2.z, f2.w), f2h2(f3.x, f3.y), f2h2(f3.z, f3.w));
        } else {
            const __half* p = Ah + (size_t)(m0 + srow) * ldA + k0 + cc * 8;
            c0 = *(const uint4*)(p);
            c1 = *(const uint4*)(p + 8);
        }
    };
    auto loadB = [&](int k0, uint4& c0, uint4& c1) {
        const __half* p = Bp + (size_t)(n0 + srow) * ldB + k0 + cc * 8;
        c0 = *(const uint4*)(p);
        c1 = *(const uint4*)(p + 8);
    };

    uint4 a0, a1, b0, b1;
    loadA(0, a0, a1);
    loadB(0, b0, b1);

    for (int kt = 0; kt < KT; kt++) {
        const int buf = kt & 1;
        // stage current tile into smem (swizzled chunks)
        *(uint4*)&As[buf][srow * 32 + ((cc       ^ ssw) << 3)] = a0;
        *(uint4*)&As[buf][srow * 32 + (((cc + 1) ^ ssw) << 3)] = a1;
        *(uint4*)&Bs[buf][srow * 32 + ((cc       ^ ssw) << 3)] = b0;
        *(uint4*)&Bs[buf][srow * 32 + (((cc + 1) ^ ssw) << 3)] = b1;

        uint4 na0, na1, nb0, nb1;
        if (kt + 1 < KT) {
            loadA((kt + 1) * 32, na0, na1);
            loadB((kt + 1) * 32, nb0, nb1);
        }
        __syncthreads();

        // compute on buf
        const uint32_t Ab = As_u + buf * 8192;
        const uint32_t Bb = Bs_u + buf * 8192;
        const int frow  = lane & 15;     // row within 16-row block
        const int khalf = lane >> 4;     // which 8-halfs chunk within k16
        #pragma unroll
        for (int ks = 0; ks < 2; ks++) {
            uint32_t a[2][4];
            #pragma unroll
            for (int mi = 0; mi < 2; mi++) {
                const int r  = wm + mi * 16 + frow;
                const int ch = (ks * 2 + khalf) ^ ((r >> 1) & 3);
                ldsm_x4(a[mi], Ab + r * 64 + ch * 16);
            }
            #pragma unroll
            for (int bj = 0; bj < 4; bj++) {
                const int r  = wn + bj * 16 + frow;
                const int ch = (ks * 2 + khalf) ^ ((r >> 1) & 3);
                uint32_t t[4];
                ldsm_x4(t, Bb + r * 64 + ch * 16);
                // n-frag 2*bj = {t0,t2}, n-frag 2*bj+1 = {t1,t3}
                mma_f16(acc[0][2 * bj],     a[0], t[0], t[2]);
                mma_f16(acc[1][2 * bj],     a[1], t[0], t[2]);
                mma_f16(acc[0][2 * bj + 1], a[0], t[1], t[3]);
                mma_f16(acc[1][2 * bj + 1], a[1], t[1], t[3]);
            }
        }
        __syncthreads();
        a0 = na0; a1 = na1; b0 = nb0; b1 = nb1;
    }

    // epilogue
    const int er = lane >> 2;
    const int ec = (lane & 3) * 2;
    #pragma unroll
    for (int mi = 0; mi < 2; mi++) {
        #pragma unroll
        for (int nj = 0; nj < 8; nj++) {
            const int r = m0 + wm + mi * 16 + er;
            const int c = n0 + wn + nj * 8 + ec;
            float v0 = acc[mi][nj][0] * alpha, v1 = acc[mi][nj][1] * alpha;
            float v2 = acc[mi][nj][2] * alpha, v3 = acc[mi][nj][3] * alpha;
            if (OUTH) {
                *(__half2*)(Ch + (size_t)r * ldC + c)       = __floats2half2_rn(v0, v1);
                *(__half2*)(Ch + (size_t)(r + 8) * ldC + c) = __floats2half2_rn(v2, v3);
            } else {
                *(float2*)(Cf + (size_t)r * ldC + c)        = make_float2(v0, v1);
                *(float2*)(Cf + (size_t)(r + 8) * ldC + c)  = make_float2(v2, v3);
            }
        }
    }
}

// ---------------------------------------------------------------------------
// Legacy tf32 mma GEMM for the tiny weight folds (NN): C = A[M,K] @ B[K,N],
// fp32 inputs (cvt.rna applied to fragments), fp16 output.
// ---------------------------------------------------------------------------
#define BKP 20
__device__ __forceinline__ void cp16(void* s, const void* g) {
    unsigned sa = (unsigned)__cvta_generic_to_shared(s);
    asm volatile("cp.async.cg.shared.global [%0], [%1], 16;\n" :: "r"(sa), "l"(g));
}
__device__ __forceinline__ void cp_commit() { asm volatile("cp.async.commit_group;\n"); }
template<int NW> __device__ __forceinline__ void cp_wait() {
    asm volatile("cp.async.wait_group %0;\n" :: "n"(NW));
}
__device__ __forceinline__ void mma_m16n8k8(float* c, const uint32_t* a, const uint32_t* b) {
    asm volatile(
        "mma.sync.aligned.m16n8k8.row.col.f32.tf32.tf32.f32 "
        "{%0,%1,%2,%3}, {%4,%5,%6,%7}, {%8,%9}, {%0,%1,%2,%3};\n"
        : "+f"(c[0]), "+f"(c[1]), "+f"(c[2]), "+f"(c[3])
        : "r"(a[0]), "r"(a[1]), "r"(a[2]), "r"(a[3]), "r"(b[0]), "r"(b[1]));
}

__global__ void __launch_bounds__(256)
fold_nn(const float* __restrict__ A, const float* __restrict__ B, __half* __restrict__ C,
        int K, int ldA, int ldB, int ldC)
{
    __shared__ float As[2][128][BKP];
    __shared__ float Bs[2][128][BKP];

    const int tid = threadIdx.x;
    const int lane = tid & 31;
    const int warp = tid >> 5;
    const int wm = (warp & 3) * 32;
    const int wn = (warp >> 2) * 64;
    const int m0 = blockIdx.y * 128;
    const int n0 = blockIdx.x * 128;

    const int lr = tid >> 1;
    const int lk = (tid & 1) * 8;
    const int bn = tid & 127;
    const int bk0 = (tid >> 7) * 8;

    float acc[2][8][4];
    #pragma unroll
    for (int i = 0; i < 2; i++)
        #pragma unroll
        for (int j = 0; j < 8; j++)
            #pragma unroll
            for (int l = 0; l < 4; l++) acc[i][j][l] = 0.0f;

    const int KT = K / 16;
    float regB[8];
    {
        const float* Ag = A + (size_t)(m0 + lr) * ldA + lk;
        cp16(&As[0][lr][lk], Ag);
        cp16(&As[0][lr][lk + 4], Ag + 4);
        #pragma unroll
        for (int j = 0; j < 8; j++) regB[j] = B[(size_t)(bk0 + j) * ldB + n0 + bn];
        cp_commit();
    }
    for (int kt = 0; kt < KT; kt++) {
        const int buf = kt & 1;
        #pragma unroll
        for (int j = 0; j < 8; j++) Bs[buf][bn][bk0 + j] = regB[j];
        if (kt + 1 < KT) {
            const int nb = (kt + 1) & 1;
            const int k0 = (kt + 1) * 16;
            const float* Ag = A + (size_t)(m0 + lr) * ldA + k0 + lk;
            cp16(&As[nb][lr][lk], Ag);
            cp16(&As[nb][lr][lk + 4], Ag + 4);
            #pragma unroll
            for (int j = 0; j < 8; j++) regB[j] = B[(size_t)(k0 + bk0 + j) * ldB + n0 + bn];
            cp_commit();
            cp_wait<1>();
        } else {
            cp_wait<0>();
        }
        __syncthreads();
        const int g = lane >> 2, tg = lane & 3;
        #pragma unroll
        for (int ks = 0; ks < 2; ks++) {
            const int kk = ks * 8;
            uint32_t a[2][4];
            #pragma unroll
            for (int mi = 0; mi < 2; mi++) {
                const int r = wm + mi * 16 + g;
                a[mi][0] = tf32b(As[buf][r][kk + tg]);
                a[mi][1] = tf32b(As[buf][r + 8][kk + tg]);
                a[mi][2] = tf32b(As[buf][r][kk + tg + 4]);
                a[mi][3] = tf32b(As[buf][r + 8][kk + tg + 4]);
            }
            #pragma unroll
            for (int ni = 0; ni < 8; ni++) {
                const int n = wn + ni * 8 + g;
                uint32_t b[2] = { tf32b(Bs[buf][n][kk + tg]), tf32b(Bs[buf][n][kk + tg + 4]) };
                mma_m16n8k8(acc[0][ni], a[0], b);
                mma_m16n8k8(acc[1][ni], a[1], b);
            }
        }
        __syncthreads();
    }
    const int g = lane >> 2, tg = lane & 3;
    #pragma unroll
    for (int mi = 0; mi < 2; mi++)
        #pragma unroll
        for (int ni = 0; ni < 8; ni++) {
            const int r = m0 + wm + mi * 16 + g;
            const int c = n0 + wn + ni * 8 + tg * 2;
            *(__half2*)(C + (size_t)r * ldC + c) =
                __floats2half2_rn(acc[mi][ni][0], acc[mi][ni][1]);
            *(__half2*)(C + (size_t)(r + 8) * ldC + c) =
                __floats2half2_rn(acc[mi][ni][2], acc[mi][ni][3]);
        }
}

// ---------------------------------------------------------------------------
// v [b][s][e] -> vT [b][e][s] (fp16, 32x32 smem tiles)
// ---------------------------------------------------------------------------
__global__ void __launch_bounds__(256)
transpose_v(const __half* __restrict__ in, __half* __restrict__ out)
{
    __shared__ __half t[32][33];
    const __half* bi = in  + (size_t)blockIdx.z * SEQ * LOWD;
    __half*       bo = out + (size_t)blockIdx.z * SEQ * LOWD;
    const int x0 = blockIdx.x * 32;   // e
    const int y0 = blockIdx.y * 32;   // s
    const int tx = threadIdx.x, ty = threadIdx.y;
    #pragma unroll
    for (int i = ty; i < 32; i += 8)
        t[i][tx] = bi[(size_t)(y0 + i) * LOWD + x0 + tx];
    __syncthreads();
    #pragma unroll
    for (int i = ty; i < 32; i += 8)
        bo[(size_t)(x0 + i) * SEQ + y0 + tx] = t[tx][i];
}

// ---------------------------------------------------------------------------
// Softmax: rows of 2048 fp32 scores -> fp16 probs. Single pass, regs-resident.
// ---------------------------------------------------------------------------
__global__ void __launch_bounds__(256)
softmax_h(const float* __restrict__ P, __half* __restrict__ Ph)
{
    const size_t off = (size_t)blockIdx.x * SEQ;
    const float* row = P + off;
    __half* orow = Ph + off;
    const int t = threadIdx.x;
    const int lane = t & 31, warp = t >> 5;

    float v[8];
    {
        float4 f0 = *(const float4*)(row + t * 8);
        float4 f1 = *(const float4*)(row + t * 8 + 4);
        v[0] = f0.x; v[1] = f0.y; v[2] = f0.z; v[3] = f0.w;
        v[4] = f1.x; v[5] = f1.y; v[6] = f1.z; v[7] = f1.w;
    }
    float m = v[0];
    #pragma unroll
    for (int i = 1; i < 8; i++) m = fmaxf(m, v[i]);
    #pragma unroll
    for (int o = 16; o; o >>= 1) m = fmaxf(m, __shfl_xor_sync(0xffffffffu, m, o));
    __shared__ float redm[8], reds[8];
    if (lane == 0) redm[warp] = m;
    __syncthreads();
    float gm = redm[0];
    #pragma unroll
    for (int i = 1; i < 8; i++) gm = fmaxf(gm, redm[i]);

    float s = 0.0f;
    #pragma unroll
    for (int i = 0; i < 8; i++) { v[i] = __expf(v[i] - gm); s += v[i]; }
    #pragma unroll
    for (int o = 16; o; o >>= 1) s += __shfl_xor_sync(0xffffffffu, s, o);
    if (lane == 0) reds[warp] = s;
    __syncthreads();
    float gs = 0.0f;
    #pragma unroll
    for (int i = 0; i < 8; i++) gs += reds[i];
    const float inv = 1.0f / gs;

    __half2 h[4];
    #pragma unroll
    for (int j = 0; j < 4; j++)
        h[j] = __floats2half2_rn(v[2 * j] * inv, v[2 * j + 1] * inv);
    *(uint4*)(orow + t * 8) = *(uint4*)h;
}

// ---------------------------------------------------------------------------
// Launch sequence (graph-capturable; no sync, no alloc)
// ---------------------------------------------------------------------------
extern "C" void kernel_launch(void* const* d_in, const int* in_sizes, int n_in,
                              void* d_out, int out_size)
{
    const float* Q  = (const float*)d_in[0];
    const float* K  = (const float*)d_in[1];
    const float* V  = (const float*)d_in[2];
    const float* Wr = (const float*)d_in[3];
    const float* Wq = (const float*)d_in[4];
    const float* Wk = (const float*)d_in[5];
    const float* Wv = (const float*)d_in[6];
    float* out = (float*)d_out;

    __half *pWf, *pqkv, *pvT, *pPh;
    float* pP;
    cudaGetSymbolAddress((void**)&pWf,  g_Wf);
    cudaGetSymbolAddress((void**)&pqkv, g_qkv);
    cudaGetSymbolAddress((void**)&pvT,  g_vT);
    cudaGetSymbolAddress((void**)&pP,   g_P);
    cudaGetSymbolAddress((void**)&pPh,  g_Ph);

    const long long sW  = (long long)LOWD * KDIM;
    const long long sQK = (long long)BATCH * SEQ * LOWD;   // q/k/v stride within g_qkv
    const long long sBS = (long long)SEQ * LOWD;           // per-batch q/k/v stride
    const float scale = 1.0f / sqrtf((float)LOWD);

    // 1) Fold weights: Wf[z] = Wx @ Wr  (tf32 mma, fp16 out)
    {
        dim3 grid(KDIM / 128, LOWD / 128, 1);
        fold_nn<<<grid, 256>>>(Wq, Wr, pWf,          LOWD, LOWD, KDIM, KDIM);
        fold_nn<<<grid, 256>>>(Wk, Wr, pWf + sW,     LOWD, LOWD, KDIM, KDIM);
        fold_nn<<<grid, 256>>>(Wv, Wr, pWf + 2 * sW, LOWD, LOWD, KDIM, KDIM);
    }

    // 2) Projections (fused): qkv[z] = rn16(QKV[z]) @ Wf[z]^T
    {
        dim3 grid(LOWD / 128, (BATCH * SEQ) / 128, 3);
        hgemm_nt<true, true><<<grid, 256>>>(
            Q, K, V, pWf, pqkv,
            KDIM, KDIM, KDIM, LOWD,
            0, sW, sQK, 1.0f);
    }

    // 3) vT for the NT AV GEMM
    {
        dim3 grid(LOWD / 32, SEQ / 32, BATCH);
        transpose_v<<<grid, dim3(32, 8)>>>(pqkv + 2 * sQK, pvT);
    }

    // 4) Scores: P[b] = scale * q[b] @ k[b]^T  (fp32 out)
    {
        dim3 grid(SEQ / 128, SEQ / 128, BATCH);
        hgemm_nt<false, false><<<grid, 256>>>(
            pqkv, pqkv, pqkv, pqkv + sQK, pP,
            LOWD, LOWD, LOWD, SEQ,
            sBS, sBS, (long long)SEQ * SEQ, scale);
    }

    // 5) Softmax: fp32 scores -> fp16 probs
    softmax_h<<<BATCH * SEQ, 256>>>(pP, pPh);

    // 6) AV: out[b] = Ph[b] @ vT[b]^T  (fp32 out)
    {
        dim3 grid(LOWD / 128, SEQ / 128, BATCH);
        hgemm_nt<false, false><<<grid, 256>>>(
            pPh, pPh, pPh, pvT, out,
            SEQ, SEQ, SEQ, LOWD,
            (long long)SEQ * SEQ, sBS, sBS, 1.0f);
    }
}

// round 8
// speedup vs baseline: 5.3325x; 1.1395x over previous
#include <cuda_runtime.h>
#include <cuda_fp16.h>
#include <math.h>
#include <stdint.h>

#define BATCH 8
#define SEQ   2048
#define KDIM  1024
#define LOWD  512

// ---------------------------------------------------------------------------
// Scratch (no cudaMalloc allowed)
// ---------------------------------------------------------------------------
__device__ __align__(1024) __half g_QKVh[3 * (size_t)BATCH * SEQ * KDIM]; // fp16 Q,K,V (96MB)
__device__ __align__(1024) __half g_Wf [3 * (size_t)LOWD * KDIM];         // folded weights (fp16)
__device__ __align__(1024) __half g_qkv[3 * (size_t)BATCH * SEQ * LOWD];  // q,k,v (fp16)
__device__ __align__(1024) __half g_vT [(size_t)BATCH * SEQ * LOWD];      // v transposed
__device__ __align__(1024) float  g_P  [(size_t)BATCH * SEQ * SEQ];       // raw scores (fp32)
__device__ __align__(1024) __half g_Ph [(size_t)BATCH * SEQ * SEQ];       // probs (fp16)

// ---------------------------------------------------------------------------
// Helpers
// ---------------------------------------------------------------------------
__device__ __forceinline__ uint32_t tf32b(float x) {
    uint32_t u; asm("cvt.rna.tf32.f32 %0, %1;" : "=r"(u) : "f"(x)); return u;
}
__device__ __forceinline__ uint32_t smem_u32(const void* p) {
    uint32_t a;
    asm("{ .reg .u64 t; cvta.to.shared.u64 t, %1; cvt.u32.u64 %0, t; }" : "=r"(a) : "l"(p));
    return a;
}
__device__ __forceinline__ void cp16(void* s, const void* g) {
    unsigned sa = (unsigned)__cvta_generic_to_shared(s);
    asm volatile("cp.async.cg.shared.global [%0], [%1], 16;\n" :: "r"(sa), "l"(g));
}
__device__ __forceinline__ void cp_commit() { asm volatile("cp.async.commit_group;\n"); }
template<int NW> __device__ __forceinline__ void cp_wait() {
    asm volatile("cp.async.wait_group %0;\n" :: "n"(NW));
}
__device__ __forceinline__ void ldsm_x4(uint32_t* r, uint32_t addr) {
    asm volatile("ldmatrix.sync.aligned.m8n8.x4.shared.b16 {%0,%1,%2,%3}, [%4];"
        : "=r"(r[0]), "=r"(r[1]), "=r"(r[2]), "=r"(r[3]) : "r"(addr));
}
__device__ __forceinline__ void mma_f16(float* c, const uint32_t* a, uint32_t b0, uint32_t b1) {
    asm volatile(
        "mma.sync.aligned.m16n8k16.row.col.f32.f16.f16.f32 "
        "{%0,%1,%2,%3}, {%4,%5,%6,%7}, {%8,%9}, {%0,%1,%2,%3};"
        : "+f"(c[0]), "+f"(c[1]), "+f"(c[2]), "+f"(c[3])
        : "r"(a[0]), "r"(a[1]), "r"(a[2]), "r"(a[3]), "r"(b0), "r"(b1));
}

// ---------------------------------------------------------------------------
// fp32 -> fp16 conversion pass for Q/K/V (z selects source tensor).
// ---------------------------------------------------------------------------
__global__ void __launch_bounds__(256)
f2h_pass(const float* __restrict__ A0, const float* __restrict__ A1,
         const float* __restrict__ A2, __half* __restrict__ out)
{
    const int z = blockIdx.z;
    const float* src = (z == 1) ? A1 : ((z == 2) ? A2 : A0);
    __half* dst = out + (size_t)z * BATCH * SEQ * KDIM;
    const size_t i = ((size_t)blockIdx.x * 256 + threadIdx.x) * 8;
    float4 f0 = *(const float4*)(src + i);
    float4 f1 = *(const float4*)(src + i + 4);
    __half2 h[4];
    h[0] = __floats2half2_rn(f0.x, f0.y);
    h[1] = __floats2half2_rn(f0.z, f0.w);
    h[2] = __floats2half2_rn(f1.x, f1.y);
    h[3] = __floats2half2_rn(f1.z, f1.w);
    *(uint4*)(dst + i) = *(uint4*)h;
}

// ---------------------------------------------------------------------------
// Pure-fp16 NT GEMM with 3-stage cp.async pipeline.
// C[m][n] = alpha * sum_k A[m][k] * B[n][k];  BM=BN=128, BK=32.
// 8 warps (4x2), warp tile 32x64, ldmatrix + XOR swizzle (same as proven R5).
// OUTH: write C fp16, else fp32. blockIdx.z batches via strides.
// Requires M%128==0, N%128==0, K%64==0 (KT>=2).
// ---------------------------------------------------------------------------
template<bool OUTH>
__global__ void __launch_bounds__(256, 2)
hgemm_nt(const __half* __restrict__ A_, const __half* __restrict__ B_, void* C_,
         int K, int ldA, int ldB, int ldC,
         long long sA, long long sB, long long sC, float alpha)
{
    constexpr int ST = 3;
    __shared__ __align__(16) __half As[ST][128 * 32];   // 24 KB
    __shared__ __align__(16) __half Bs[ST][128 * 32];   // 24 KB

    const __half* Ap = A_ + (size_t)blockIdx.z * sA;
    const __half* Bp = B_ + (size_t)blockIdx.z * sB;
    float*  Cf = OUTH ? nullptr : ((float*)C_ + (size_t)blockIdx.z * sC);
    __half* Ch = OUTH ? ((__half*)C_ + (size_t)blockIdx.z * sC) : nullptr;

    const int tid  = threadIdx.x;
    const int lane = tid & 31;
    const int warp = tid >> 5;
    const int wm   = (warp & 3) * 32;
    const int wn   = (warp >> 2) * 64;
    const int m0   = blockIdx.y * 128;
    const int n0   = blockIdx.x * 128;

    // staging: each thread owns one row-half (2 chunks of 8 halfs = 2x16B)
    const int srow = tid >> 1;
    const int cc   = (tid & 1) * 2;
    const int ssw  = (srow >> 1) & 3;

    float acc[2][8][4];
    #pragma unroll
    for (int i = 0; i < 2; i++)
        #pragma unroll
        for (int j = 0; j < 8; j++)
            #pragma unroll
            for (int l = 0; l < 4; l++) acc[i][j][l] = 0.0f;

    const uint32_t As_u = smem_u32(As);
    const uint32_t Bs_u = smem_u32(Bs);
    const int KT = K / 32;

    auto stage_in = [&](int st, int k0) {
        const __half* pa = Ap + (size_t)(m0 + srow) * ldA + k0 + cc * 8;
        cp16(&As[st][srow * 32 + ((cc       ^ ssw) << 3)], pa);
        cp16(&As[st][srow * 32 + (((cc + 1) ^ ssw) << 3)], pa + 8);
        const __half* pb = Bp + (size_t)(n0 + srow) * ldB + k0 + cc * 8;
        cp16(&Bs[st][srow * 32 + ((cc       ^ ssw) << 3)], pb);
        cp16(&Bs[st][srow * 32 + (((cc + 1) ^ ssw) << 3)], pb + 8);
        cp_commit();
    };

    stage_in(0, 0);
    stage_in(1, 32);

    int cbuf = 0;   // stage holding tile kt
    for (int kt = 0; kt < KT; kt++) {
        cp_wait<ST - 2>();      // tile kt resident
        __syncthreads();        // also: everyone done computing tile kt-1

        // refill the stage freed by tile kt-1 (safe after the sync)
        if (kt + 2 < KT) {
            int st = cbuf - 1; if (st < 0) st += ST;
            stage_in(st, (kt + 2) * 32);
        } else {
            cp_commit();        // keep group accounting uniform
        }

        const uint32_t Ab = As_u + cbuf * 8192;
        const uint32_t Bb = Bs_u + cbuf * 8192;
        const int frow  = lane & 15;
        const int khalf = lane >> 4;
        #pragma unroll
        for (int ks = 0; ks < 2; ks++) {
            uint32_t a[2][4];
            #pragma unroll
            for (int mi = 0; mi < 2; mi++) {
                const int r  = wm + mi * 16 + frow;
                const int ch = (ks * 2 + khalf) ^ ((r >> 1) & 3);
                ldsm_x4(a[mi], Ab + r * 64 + ch * 16);
            }
            #pragma unroll
            for (int bj = 0; bj < 4; bj++) {
                const int r  = wn + bj * 16 + frow;
                const int ch = (ks * 2 + khalf) ^ ((r >> 1) & 3);
                uint32_t t[4];
                ldsm_x4(t, Bb + r * 64 + ch * 16);
                mma_f16(acc[0][2 * bj],     a[0], t[0], t[2]);
                mma_f16(acc[1][2 * bj],     a[1], t[0], t[2]);
                mma_f16(acc[0][2 * bj + 1], a[0], t[1], t[3]);
                mma_f16(acc[1][2 * bj + 1], a[1], t[1], t[3]);
            }
        }
        if (++cbuf == ST) cbuf = 0;
    }

    // epilogue
    const int er = lane >> 2;
    const int ec = (lane & 3) * 2;
    #pragma unroll
    for (int mi = 0; mi < 2; mi++) {
        #pragma unroll
        for (int nj = 0; nj < 8; nj++) {
            const int r = m0 + wm + mi * 16 + er;
            const int c = n0 + wn + nj * 8 + ec;
            float v0 = acc[mi][nj][0] * alpha, v1 = acc[mi][nj][1] * alpha;
            float v2 = acc[mi][nj][2] * alpha, v3 = acc[mi][nj][3] * alpha;
            if (OUTH) {
                *(__half2*)(Ch + (size_t)r * ldC + c)       = __floats2half2_rn(v0, v1);
                *(__half2*)(Ch + (size_t)(r + 8) * ldC + c) = __floats2half2_rn(v2, v3);
            } else {
                *(float2*)(Cf + (size_t)r * ldC + c)        = make_float2(v0, v1);
                *(float2*)(Cf + (size_t)(r + 8) * ldC + c)  = make_float2(v2, v3);
            }
        }
    }
}

// ---------------------------------------------------------------------------
// Legacy tf32 mma GEMM for the tiny weight folds (NN): fp32 in, fp16 out.
// ---------------------------------------------------------------------------
#define BKP 20
__device__ __forceinline__ void mma_m16n8k8(float* c, const uint32_t* a, const uint32_t* b) {
    asm volatile(
        "mma.sync.aligned.m16n8k8.row.col.f32.tf32.tf32.f32 "
        "{%0,%1,%2,%3}, {%4,%5,%6,%7}, {%8,%9}, {%0,%1,%2,%3};\n"
        : "+f"(c[0]), "+f"(c[1]), "+f"(c[2]), "+f"(c[3])
        : "r"(a[0]), "r"(a[1]), "r"(a[2]), "r"(a[3]), "r"(b[0]), "r"(b[1]));
}

__global__ void __launch_bounds__(256)
fold_nn(const float* __restrict__ A, const float* __restrict__ B, __half* __restrict__ C,
        int K, int ldA, int ldB, int ldC)
{
    __shared__ float As[2][128][BKP];
    __shared__ float Bs[2][128][BKP];

    const int tid = threadIdx.x;
    const int lane = tid & 31;
    const int warp = tid >> 5;
    const int wm = (warp & 3) * 32;
    const int wn = (warp >> 2) * 64;
    const int m0 = blockIdx.y * 128;
    const int n0 = blockIdx.x * 128;

    const int lr = tid >> 1;
    const int lk = (tid & 1) * 8;
    const int bn = tid & 127;
    const int bk0 = (tid >> 7) * 8;

    float acc[2][8][4];
    #pragma unroll
    for (int i = 0; i < 2; i++)
        #pragma unroll
        for (int j = 0; j < 8; j++)
            #pragma unroll
            for (int l = 0; l < 4; l++) acc[i][j][l] = 0.0f;

    const int KT = K / 16;
    float regB[8];
    {
        const float* Ag = A + (size_t)(m0 + lr) * ldA + lk;
        cp16(&As[0][lr][lk], Ag);
        cp16(&As[0][lr][lk + 4], Ag + 4);
        #pragma unroll
        for (int j = 0; j < 8; j++) regB[j] = B[(size_t)(bk0 + j) * ldB + n0 + bn];
        cp_commit();
    }
    for (int kt = 0; kt < KT; kt++) {
        const int buf = kt & 1;
        #pragma unroll
        for (int j = 0; j < 8; j++) Bs[buf][bn][bk0 + j] = regB[j];
        if (kt + 1 < KT) {
            const int nb = (kt + 1) & 1;
            const int k0 = (kt + 1) * 16;
            const float* Ag = A + (size_t)(m0 + lr) * ldA + k0 + lk;
            cp16(&As[nb][lr][lk], Ag);
            cp16(&As[nb][lr][lk + 4], Ag + 4);
            #pragma unroll
            for (int j = 0; j < 8; j++) regB[j] = B[(size_t)(k0 + bk0 + j) * ldB + n0 + bn];
            cp_commit();
            cp_wait<1>();
        } else {
            cp_wait<0>();
        }
        __syncthreads();
        const int g = lane >> 2, tg = lane & 3;
        #pragma unroll
        for (int ks = 0; ks < 2; ks++) {
            const int kk = ks * 8;
            uint32_t a[2][4];
            #pragma unroll
            for (int mi = 0; mi < 2; mi++) {
                const int r = wm + mi * 16 + g;
                a[mi][0] = tf32b(As[buf][r][kk + tg]);
                a[mi][1] = tf32b(As[buf][r + 8][kk + tg]);
                a[mi][2] = tf32b(As[buf][r][kk + tg + 4]);
                a[mi][3] = tf32b(As[buf][r + 8][kk + tg + 4]);
            }
            #pragma unroll
            for (int ni = 0; ni < 8; ni++) {
                const int n = wn + ni * 8 + g;
                uint32_t b[2] = { tf32b(Bs[buf][n][kk + tg]), tf32b(Bs[buf][n][kk + tg + 4]) };
                mma_m16n8k8(acc[0][ni], a[0], b);
                mma_m16n8k8(acc[1][ni], a[1], b);
            }
        }
        __syncthreads();
    }
    const int g = lane >> 2, tg = lane & 3;
    #pragma unroll
    for (int mi = 0; mi < 2; mi++)
        #pragma unroll
        for (int ni = 0; ni < 8; ni++) {
            const int r = m0 + wm + mi * 16 + g;
            const int c = n0 + wn + ni * 8 + tg * 2;
            *(__half2*)(C + (size_t)r * ldC + c) =
                __floats2half2_rn(acc[mi][ni][0], acc[mi][ni][1]);
            *(__half2*)(C + (size_t)(r + 8) * ldC + c) =
                __floats2half2_rn(acc[mi][ni][2], acc[mi][ni][3]);
        }
}

// ---------------------------------------------------------------------------
// v [b][s][e] -> vT [b][e][s] (fp16, 32x32 smem tiles)
// ---------------------------------------------------------------------------
__global__ void __launch_bounds__(256)
transpose_v(const __half* __restrict__ in, __half* __restrict__ out)
{
    __shared__ __half t[32][33];
    const __half* bi = in  + (size_t)blockIdx.z * SEQ * LOWD;
    __half*       bo = out + (size_t)blockIdx.z * SEQ * LOWD;
    const int x0 = blockIdx.x * 32;
    const int y0 = blockIdx.y * 32;
    const int tx = threadIdx.x, ty = threadIdx.y;
    #pragma unroll
    for (int i = ty; i < 32; i += 8)
        t[i][tx] = bi[(size_t)(y0 + i) * LOWD + x0 + tx];
    __syncthreads();
    #pragma unroll
    for (int i = ty; i < 32; i += 8)
        bo[(size_t)(x0 + i) * SEQ + y0 + tx] = t[tx][i];
}

// ---------------------------------------------------------------------------
// Softmax: rows of 2048 fp32 scores -> fp16 probs. Single pass, regs-resident.
// ---------------------------------------------------------------------------
__global__ void __launch_bounds__(256)
softmax_h(const float* __restrict__ P, __half* __restrict__ Ph)
{
    const size_t off = (size_t)blockIdx.x * SEQ;
    const float* row = P + off;
    __half* orow = Ph + off;
    const int t = threadIdx.x;
    const int lane = t & 31, warp = t >> 5;

    float v[8];
    {
        float4 f0 = *(const float4*)(row + t * 8);
        float4 f1 = *(const float4*)(row + t * 8 + 4);
        v[0] = f0.x; v[1] = f0.y; v[2] = f0.z; v[3] = f0.w;
        v[4] = f1.x; v[5] = f1.y; v[6] = f1.z; v[7] = f1.w;
    }
    float m = v[0];
    #pragma unroll
    for (int i = 1; i < 8; i++) m = fmaxf(m, v[i]);
    #pragma unroll
    for (int o = 16; o; o >>= 1) m = fmaxf(m, __shfl_xor_sync(0xffffffffu, m, o));
    __shared__ float redm[8], reds[8];
    if (lane == 0) redm[warp] = m;
    __syncthreads();
    float gm = redm[0];
    #pragma unroll
    for (int i = 1; i < 8; i++) gm = fmaxf(gm, redm[i]);

    float s = 0.0f;
    #pragma unroll
    for (int i = 0; i < 8; i++) { v[i] = __expf(v[i] - gm); s += v[i]; }
    #pragma unroll
    for (int o = 16; o; o >>= 1) s += __shfl_xor_sync(0xffffffffu, s, o);
    if (lane == 0) reds[warp] = s;
    __syncthreads();
    float gs = 0.0f;
    #pragma unroll
    for (int i = 0; i < 8; i++) gs += reds[i];
    const float inv = 1.0f / gs;

    __half2 h[4];
    #pragma unroll
    for (int j = 0; j < 4; j++)
        h[j] = __floats2half2_rn(v[2 * j] * inv, v[2 * j + 1] * inv);
    *(uint4*)(orow + t * 8) = *(uint4*)h;
}

// ---------------------------------------------------------------------------
// Launch sequence (graph-capturable; no sync, no alloc)
// ---------------------------------------------------------------------------
extern "C" void kernel_launch(void* const* d_in, const int* in_sizes, int n_in,
                              void* d_out, int out_size)
{
    const float* Q  = (const float*)d_in[0];
    const float* K  = (const float*)d_in[1];
    const float* V  = (const float*)d_in[2];
    const float* Wr = (const float*)d_in[3];
    const float* Wq = (const float*)d_in[4];
    const float* Wk = (const float*)d_in[5];
    const float* Wv = (const float*)d_in[6];
    float* out = (float*)d_out;

    __half *pQKVh, *pWf, *pqkv, *pvT, *pPh;
    float* pP;
    cudaGetSymbolAddress((void**)&pQKVh, g_QKVh);
    cudaGetSymbolAddress((void**)&pWf,   g_Wf);
    cudaGetSymbolAddress((void**)&pqkv,  g_qkv);
    cudaGetSymbolAddress((void**)&pvT,   g_vT);
    cudaGetSymbolAddress((void**)&pP,    g_P);
    cudaGetSymbolAddress((void**)&pPh,   g_Ph);

    const long long sIN = (long long)BATCH * SEQ * KDIM;   // fp16 Q/K/V stride
    const long long sW  = (long long)LOWD * KDIM;
    const long long sQK = (long long)BATCH * SEQ * LOWD;   // q/k/v stride in g_qkv
    const long long sBS = (long long)SEQ * LOWD;           // per-batch q/k/v stride
    const float scale = 1.0f / sqrtf((float)LOWD);

    // 0) Convert Q,K,V fp32 -> fp16
    {
        dim3 grid((unsigned)(sIN / (256 * 8)), 1, 3);
        f2h_pass<<<grid, 256>>>(Q, K, V, pQKVh);
    }

    // 1) Fold weights: Wf[z] = Wx @ Wr  (tf32 mma, fp16 out)
    {
        dim3 grid(KDIM / 128, LOWD / 128, 1);
        fold_nn<<<grid, 256>>>(Wq, Wr, pWf,          LOWD, LOWD, KDIM, KDIM);
        fold_nn<<<grid, 256>>>(Wk, Wr, pWf + sW,     LOWD, LOWD, KDIM, KDIM);
        fold_nn<<<grid, 256>>>(Wv, Wr, pWf + 2 * sW, LOWD, LOWD, KDIM, KDIM);
    }

    // 2) Projections (fused over z): qkv[z] = QKVh[z] @ Wf[z]^T  (fp16 out)
    {
        dim3 grid(LOWD / 128, (BATCH * SEQ) / 128, 3);
        hgemm_nt<true><<<grid, 256>>>(
            pQKVh, pWf, pqkv, KDIM, KDIM, KDIM, LOWD, sIN, sW, sQK, 1.0f);
    }

    // 3) vT for the NT AV GEMM
    {
        dim3 grid(LOWD / 32, SEQ / 32, BATCH);
        transpose_v<<<grid, dim3(32, 8)>>>(pqkv + 2 * sQK, pvT);
    }

    // 4) Scores: P[b] = scale * q[b] @ k[b]^T  (fp32 out)
    {
        dim3 grid(SEQ / 128, SEQ / 128, BATCH);
        hgemm_nt<false><<<grid, 256>>>(
            pqkv, pqkv + sQK, pP, LOWD, LOWD, LOWD, SEQ,
            sBS, sBS, (long long)SEQ * SEQ, scale);
    }

    // 5) Softmax: fp32 scores -> fp16 probs
    softmax_h<<<BATCH * SEQ, 256>>>(pP, pPh);

    // 6) AV: out[b] = Ph[b] @ vT[b]^T  (fp32 out)
    {
        dim3 grid(LOWD / 128, SEQ / 128, BATCH);
        hgemm_nt<false><<<grid, 256>>>(
            pPh, pvT, out, SEQ, SEQ, SEQ, LOWD,
            (long long)SEQ * SEQ, sBS, sBS, 1.0f);
    }
}

// round 11
// speedup vs baseline: 5.8029x; 1.0882x over previous
#include <cuda_runtime.h>
#include <cuda_fp16.h>
#include <math.h>
#include <stdint.h>

#define BATCH 8
#define SEQ   2048
#define KDIM  1024
#define LOWD  512

// ---------------------------------------------------------------------------
// Scratch (no cudaMalloc allowed)
// ---------------------------------------------------------------------------
__device__ __align__(1024) __half g_QKVh[3 * (size_t)BATCH * SEQ * KDIM]; // fp16 Q,K,V
__device__ __align__(1024) __half g_Wf [3 * (size_t)LOWD * KDIM];         // folded weights
__device__ __align__(1024) __half g_qkv[3 * (size_t)BATCH * SEQ * LOWD];  // q,k,v
__device__ __align__(1024) __half g_vT [(size_t)BATCH * SEQ * LOWD];      // v transposed
__device__ __align__(1024) float  g_P  [(size_t)BATCH * SEQ * SEQ];       // raw scores (fp32)
__device__ __align__(1024) __half g_Ph [(size_t)BATCH * SEQ * SEQ];       // probs (fp16)

// ---------------------------------------------------------------------------
// Helpers
// ---------------------------------------------------------------------------
__device__ __forceinline__ uint32_t tf32b(float x) {
    uint32_t u; asm("cvt.rna.tf32.f32 %0, %1;" : "=r"(u) : "f"(x)); return u;
}
__device__ __forceinline__ uint32_t smem_u32(const void* p) {
    uint32_t a;
    asm("{ .reg .u64 t; cvta.to.shared.u64 t, %1; cvt.u32.u64 %0, t; }" : "=r"(a) : "l"(p));
    return a;
}
__device__ __forceinline__ void cp16(void* s, const void* g) {
    unsigned sa = (unsigned)__cvta_generic_to_shared(s);
    asm volatile("cp.async.cg.shared.global [%0], [%1], 16;\n" :: "r"(sa), "l"(g));
}
__device__ __forceinline__ void cp_commit() { asm volatile("cp.async.commit_group;\n"); }
template<int NW> __device__ __forceinline__ void cp_wait() {
    asm volatile("cp.async.wait_group %0;\n" :: "n"(NW));
}
__device__ __forceinline__ void ldsm_x4(uint32_t* r, uint32_t addr) {
    asm volatile("ldmatrix.sync.aligned.m8n8.x4.shared.b16 {%0,%1,%2,%3}, [%4];"
        : "=r"(r[0]), "=r"(r[1]), "=r"(r[2]), "=r"(r[3]) : "r"(addr));
}
__device__ __forceinline__ void mma_f16(float* c, const uint32_t* a, uint32_t b0, uint32_t b1) {
    asm volatile(
        "mma.sync.aligned.m16n8k16.row.col.f32.f16.f16.f32 "
        "{%0,%1,%2,%3}, {%4,%5,%6,%7}, {%8,%9}, {%0,%1,%2,%3};"
        : "+f"(c[0]), "+f"(c[1]), "+f"(c[2]), "+f"(c[3])
        : "r"(a[0]), "r"(a[1]), "r"(a[2]), "r"(a[3]), "r"(b0), "r"(b1));
}

// ---------------------------------------------------------------------------
// fp32 -> fp16 conversion pass for Q/K/V (z selects source tensor).
// ---------------------------------------------------------------------------
__global__ void __launch_bounds__(256)
f2h_pass(const float* __restrict__ A0, const float* __restrict__ A1,
         const float* __restrict__ A2, __half* __restrict__ out)
{
    const int z = blockIdx.z;
    const float* src = (z == 1) ? A1 : ((z == 2) ? A2 : A0);
    __half* dst = out + (size_t)z * BATCH * SEQ * KDIM;
    const size_t i = ((size_t)blockIdx.x * 256 + threadIdx.x) * 8;
    float4 f0 = *(const float4*)(src + i);
    float4 f1 = *(const float4*)(src + i + 4);
    __half2 h[4];
    h[0] = __floats2half2_rn(f0.x, f0.y);
    h[1] = __floats2half2_rn(f0.z, f0.w);
    h[2] = __floats2half2_rn(f1.x, f1.y);
    h[3] = __floats2half2_rn(f1.z, f1.w);
    *(uint4*)(dst + i) = *(uint4*)h;
}

// ---------------------------------------------------------------------------
// Pure-fp16 NT GEMM with 3-stage cp.async pipeline (proven R8 kernel).
// ---------------------------------------------------------------------------
template<bool OUTH>
__global__ void __launch_bounds__(256, 2)
hgemm_nt(const __half* __restrict__ A_, const __half* __restrict__ B_, void* C_,
         int K, int ldA, int ldB, int ldC,
         long long sA, long long sB, long long sC, float alpha)
{
    constexpr int ST = 3;
    __shared__ __align__(16) __half As[ST][128 * 32];
    __shared__ __align__(16) __half Bs[ST][128 * 32];

    const __half* Ap = A_ + (size_t)blockIdx.z * sA;
    const __half* Bp = B_ + (size_t)blockIdx.z * sB;
    float*  Cf = OUTH ? nullptr : ((float*)C_ + (size_t)blockIdx.z * sC);
    __half* Ch = OUTH ? ((__half*)C_ + (size_t)blockIdx.z * sC) : nullptr;

    const int tid  = threadIdx.x;
    const int lane = tid & 31;
    const int warp = tid >> 5;
    const int wm   = (warp & 3) * 32;
    const int wn   = (warp >> 2) * 64;
    const int m0   = blockIdx.y * 128;
    const int n0   = blockIdx.x * 128;

    const int srow = tid >> 1;
    const int cc   = (tid & 1) * 2;
    const int ssw  = (srow >> 1) & 3;

    float acc[2][8][4];
    #pragma unroll
    for (int i = 0; i < 2; i++)
        #pragma unroll
        for (int j = 0; j < 8; j++)
            #pragma unroll
            for (int l = 0; l < 4; l++) acc[i][j][l] = 0.0f;

    const uint32_t As_u = smem_u32(As);
    const uint32_t Bs_u = smem_u32(Bs);
    const int KT = K / 32;

    auto stage_in = [&](int st, int k0) {
        const __half* pa = Ap + (size_t)(m0 + srow) * ldA + k0 + cc * 8;
        cp16(&As[st][srow * 32 + ((cc       ^ ssw) << 3)], pa);
        cp16(&As[st][srow * 32 + (((cc + 1) ^ ssw) << 3)], pa + 8);
        const __half* pb = Bp + (size_t)(n0 + srow) * ldB + k0 + cc * 8;
        cp16(&Bs[st][srow * 32 + ((cc       ^ ssw) << 3)], pb);
        cp16(&Bs[st][srow * 32 + (((cc + 1) ^ ssw) << 3)], pb + 8);
        cp_commit();
    };

    stage_in(0, 0);
    stage_in(1, 32);

    int cbuf = 0;
    for (int kt = 0; kt < KT; kt++) {
        cp_wait<ST - 2>();
        __syncthreads();

        if (kt + 2 < KT) {
            int st = cbuf - 1; if (st < 0) st += ST;
            stage_in(st, (kt + 2) * 32);
        } else {
            cp_commit();
        }

        const uint32_t Ab = As_u + cbuf * 8192;
        const uint32_t Bb = Bs_u + cbuf * 8192;
        const int frow  = lane & 15;
        const int khalf = lane >> 4;
        #pragma unroll
        for (int ks = 0; ks < 2; ks++) {
            uint32_t a[2][4];
            #pragma unroll
            for (int mi = 0; mi < 2; mi++) {
                const int r  = wm + mi * 16 + frow;
                const int ch = (ks * 2 + khalf) ^ ((r >> 1) & 3);
                ldsm_x4(a[mi], Ab + r * 64 + ch * 16);
            }
            #pragma unroll
            for (int bj = 0; bj < 4; bj++) {
                const int r  = wn + bj * 16 + frow;
                const int ch = (ks * 2 + khalf) ^ ((r >> 1) & 3);
                uint32_t t[4];
                ldsm_x4(t, Bb + r * 64 + ch * 16);
                mma_f16(acc[0][2 * bj],     a[0], t[0], t[2]);
                mma_f16(acc[1][2 * bj],     a[1], t[0], t[2]);
                mma_f16(acc[0][2 * bj + 1], a[0], t[1], t[3]);
                mma_f16(acc[1][2 * bj + 1], a[1], t[1], t[3]);
            }
        }
        if (++cbuf == ST) cbuf = 0;
    }

    const int er = lane >> 2;
    const int ec = (lane & 3) * 2;
    #pragma unroll
    for (int mi = 0; mi < 2; mi++) {
        #pragma unroll
        for (int nj = 0; nj < 8; nj++) {
            const int r = m0 + wm + mi * 16 + er;
            const int c = n0 + wn + nj * 8 + ec;
            float v0 = acc[mi][nj][0] * alpha, v1 = acc[mi][nj][1] * alpha;
            float v2 = acc[mi][nj][2] * alpha, v3 = acc[mi][nj][3] * alpha;
            if (OUTH) {
                *(__half2*)(Ch + (size_t)r * ldC + c)       = __floats2half2_rn(v0, v1);
                *(__half2*)(Ch + (size_t)(r + 8) * ldC + c) = __floats2half2_rn(v2, v3);
            } else {
                *(float2*)(Cf + (size_t)r * ldC + c)        = make_float2(v0, v1);
                *(float2*)(Cf + (size_t)(r + 8) * ldC + c)  = make_float2(v2, v3);
            }
        }
    }
}

// ---------------------------------------------------------------------------
// Fused weight folds (tf32 mma, NN): Wf[z] = W{q,k,v} @ Wr, fp16 out.
// Single launch with z selecting the A operand (only change vs the R8 pass).
// ---------------------------------------------------------------------------
#define BKP 20
__device__ __forceinline__ void mma_m16n8k8(float* c, const uint32_t* a, const uint32_t* b) {
    asm volatile(
        "mma.sync.aligned.m16n8k8.row.col.f32.tf32.tf32.f32 "
        "{%0,%1,%2,%3}, {%4,%5,%6,%7}, {%8,%9}, {%0,%1,%2,%3};\n"
        : "+f"(c[0]), "+f"(c[1]), "+f"(c[2]), "+f"(c[3])
        : "r"(a[0]), "r"(a[1]), "r"(a[2]), "r"(a[3]), "r"(b[0]), "r"(b[1]));
}

__global__ void __launch_bounds__(256)
fold_nn(const float* __restrict__ A0, const float* __restrict__ A1,
        const float* __restrict__ A2, const float* __restrict__ B,
        __half* __restrict__ C_, int K, int ldA, int ldB, int ldC, long long sC)
{
    __shared__ float As[2][128][BKP];
    __shared__ float Bs[2][128][BKP];

    const int z = blockIdx.z;
    const float* A = (z == 1) ? A1 : ((z == 2) ? A2 : A0);
    __half* C = C_ + (size_t)z * sC;

    const int tid = threadIdx.x;
    const int lane = tid & 31;
    const int warp = tid >> 5;
    const int wm = (warp & 3) * 32;
    const int wn = (warp >> 2) * 64;
    const int m0 = blockIdx.y * 128;
    const int n0 = blockIdx.x * 128;

    const int lr = tid >> 1;
    const int lk = (tid & 1) * 8;
    const int bn = tid & 127;
    const int bk0 = (tid >> 7) * 8;

    float acc[2][8][4];
    #pragma unroll
    for (int i = 0; i < 2; i++)
        #pragma unroll
        for (int j = 0; j < 8; j++)
            #pragma unroll
            for (int l = 0; l < 4; l++) acc[i][j][l] = 0.0f;

    const int KT = K / 16;
    float regB[8];
    {
        const float* Ag = A + (size_t)(m0 + lr) * ldA + lk;
        cp16(&As[0][lr][lk], Ag);
        cp16(&As[0][lr][lk + 4], Ag + 4);
        #pragma unroll
        for (int j = 0; j < 8; j++) regB[j] = B[(size_t)(bk0 + j) * ldB + n0 + bn];
        cp_commit();
    }
    for (int kt = 0; kt < KT; kt++) {
        const int buf = kt & 1;
        #pragma unroll
        for (int j = 0; j < 8; j++) Bs[buf][bn][bk0 + j] = regB[j];
        if (kt + 1 < KT) {
            const int nb = (kt + 1) & 1;
            const int k0 = (kt + 1) * 16;
            const float* Ag = A + (size_t)(m0 + lr) * ldA + k0 + lk;
            cp16(&As[nb][lr][lk], Ag);
            cp16(&As[nb][lr][lk + 4], Ag + 4);
            #pragma unroll
            for (int j = 0; j < 8; j++) regB[j] = B[(size_t)(k0 + bk0 + j) * ldB + n0 + bn];
            cp_commit();
            cp_wait<1>();
        } else {
            cp_wait<0>();
        }
        __syncthreads();
        const int g = lane >> 2, tg = lane & 3;
        #pragma unroll
        for (int ks = 0; ks < 2; ks++) {
            const int kk = ks * 8;
            uint32_t a[2][4];
            #pragma unroll
            for (int mi = 0; mi < 2; mi++) {
                const int r = wm + mi * 16 + g;
                a[mi][0] = tf32b(As[buf][r][kk + tg]);
                a[mi][1] = tf32b(As[buf][r + 8][kk + tg]);
                a[mi][2] = tf32b(As[buf][r][kk + tg + 4]);
                a[mi][3] = tf32b(As[buf][r + 8][kk + tg + 4]);
            }
            #pragma unroll
            for (int ni = 0; ni < 8; ni++) {
                const int n = wn + ni * 8 + g;
                uint32_t b[2] = { tf32b(Bs[buf][n][kk + tg]), tf32b(Bs[buf][n][kk + tg + 4]) };
                mma_m16n8k8(acc[0][ni], a[0], b);
                mma_m16n8k8(acc[1][ni], a[1], b);
            }
        }
        __syncthreads();
    }
    const int g = lane >> 2, tg = lane & 3;
    #pragma unroll
    for (int mi = 0; mi < 2; mi++)
        #pragma unroll
        for (int ni = 0; ni < 8; ni++) {
            const int r = m0 + wm + mi * 16 + g;
            const int c = n0 + wn + ni * 8 + tg * 2;
            *(__half2*)(C + (size_t)r * ldC + c) =
                __floats2half2_rn(acc[mi][ni][0], acc[mi][ni][1]);
            *(__half2*)(C + (size_t)(r + 8) * ldC + c) =
                __floats2half2_rn(acc[mi][ni][2], acc[mi][ni][3]);
        }
}

// ---------------------------------------------------------------------------
// v [b][s][e] -> vT [b][e][s] (fp16, 32x32 smem tiles)
// ---------------------------------------------------------------------------
__global__ void __launch_bounds__(256)
transpose_v(const __half* __restrict__ in, __half* __restrict__ out)
{
    __shared__ __half t[32][33];
    const __half* bi = in  + (size_t)blockIdx.z * SEQ * LOWD;
    __half*       bo = out + (size_t)blockIdx.z * SEQ * LOWD;
    const int x0 = blockIdx.x * 32;
    const int y0 = blockIdx.y * 32;
    const int tx = threadIdx.x, ty = threadIdx.y;
    #pragma unroll
    for (int i = ty; i < 32; i += 8)
        t[i][tx] = bi[(size_t)(y0 + i) * LOWD + x0 + tx];
    __syncthreads();
    #pragma unroll
    for (int i = ty; i < 32; i += 8)
        bo[(size_t)(x0 + i) * SEQ + y0 + tx] = t[tx][i];
}

// ---------------------------------------------------------------------------
// Softmax: rows of 2048 fp32 scores -> fp16 probs. Single pass, regs-resident.
// ---------------------------------------------------------------------------
__global__ void __launch_bounds__(256)
softmax_h(const float* __restrict__ P, __half* __restrict__ Ph)
{
    const size_t off = (size_t)blockIdx.x * SEQ;
    const float* row = P + off;
    __half* orow = Ph + off;
    const int t = threadIdx.x;
    const int lane = t & 31, warp = t >> 5;

    float v[8];
    {
        float4 f0 = *(const float4*)(row + t * 8);
        float4 f1 = *(const float4*)(row + t * 8 + 4);
        v[0] = f0.x; v[1] = f0.y; v[2] = f0.z; v[3] = f0.w;
        v[4] = f1.x; v[5] = f1.y; v[6] = f1.z; v[7] = f1.w;
    }
    float m = v[0];
    #pragma unroll
    for (int i = 1; i < 8; i++) m = fmaxf(m, v[i]);
    #pragma unroll
    for (int o = 16; o; o >>= 1) m = fmaxf(m, __shfl_xor_sync(0xffffffffu, m, o));
    __shared__ float redm[8], reds[8];
    if (lane == 0) redm[warp] = m;
    __syncthreads();
    float gm = redm[0];
    #pragma unroll
    for (int i = 1; i < 8; i++) gm = fmaxf(gm, redm[i]);

    float s = 0.0f;
    #pragma unroll
    for (int i = 0; i < 8; i++) { v[i] = __expf(v[i] - gm); s += v[i]; }
    #pragma unroll
    for (int o = 16; o; o >>= 1) s += __shfl_xor_sync(0xffffffffu, s, o);
    if (lane == 0) reds[warp] = s;
    __syncthreads();
    float gs = 0.0f;
    #pragma unroll
    for (int i = 0; i < 8; i++) gs += reds[i];
    const float inv = 1.0f / gs;

    __half2 h[4];
    #pragma unroll
    for (int j = 0; j < 4; j++)
        h[j] = __floats2half2_rn(v[2 * j] * inv, v[2 * j + 1] * inv);
    *(uint4*)(orow + t * 8) = *(uint4*)h;
}

// ---------------------------------------------------------------------------
// Launch sequence (graph-capturable; no sync, no alloc)
// ---------------------------------------------------------------------------
extern "C" void kernel_launch(void* const* d_in, const int* in_sizes, int n_in,
                              void* d_out, int out_size)
{
    const float* Q  = (const float*)d_in[0];
    const float* K  = (const float*)d_in[1];
    const float* V  = (const float*)d_in[2];
    const float* Wr = (const float*)d_in[3];
    const float* Wq = (const float*)d_in[4];
    const float* Wk = (const float*)d_in[5];
    const float* Wv = (const float*)d_in[6];
    float* out = (float*)d_out;

    __half *pQKVh, *pWf, *pqkv, *pvT, *pPh;
    float* pP;
    cudaGetSymbolAddress((void**)&pQKVh, g_QKVh);
    cudaGetSymbolAddress((void**)&pWf,   g_Wf);
    cudaGetSymbolAddress((void**)&pqkv,  g_qkv);
    cudaGetSymbolAddress((void**)&pvT,   g_vT);
    cudaGetSymbolAddress((void**)&pP,    g_P);
    cudaGetSymbolAddress((void**)&pPh,   g_Ph);

    const long long sIN = (long long)BATCH * SEQ * KDIM;   // fp16 Q/K/V stride
    const long long sW  = (long long)LOWD * KDIM;
    const long long sQK = (long long)BATCH * SEQ * LOWD;   // q/k/v stride in g_qkv
    const long long sBS = (long long)SEQ * LOWD;           // per-batch q/k/v stride
    const float scale = 1.0f / sqrtf((float)LOWD);

    // 0) Convert Q,K,V fp32 -> fp16
    {
        dim3 grid((unsigned)(sIN / (256 * 8)), 1, 3);
        f2h_pass<<<grid, 256>>>(Q, K, V, pQKVh);
    }

    // 1) Fold weights (single fused launch over z): Wf[z] = W{q,k,v} @ Wr
    {
        dim3 grid(KDIM / 128, LOWD / 128, 3);
        fold_nn<<<grid, 256>>>(Wq, Wk, Wv, Wr, pWf, LOWD, LOWD, KDIM, KDIM, sW);
    }

    // 2) Projections (fused over z): qkv[z] = QKVh[z] @ Wf[z]^T  (fp16 out)
    {
        dim3 grid(LOWD / 128, (BATCH * SEQ) / 128, 3);
        hgemm_nt<true><<<grid, 256>>>(
            pQKVh, pWf, pqkv, KDIM, KDIM, KDIM, LOWD, sIN, sW, sQK, 1.0f);
    }

    // 3) vT for the NT AV GEMM
    {
        dim3 grid(LOWD / 32, SEQ / 32, BATCH);
        transpose_v<<<grid, dim3(32, 8)>>>(pqkv + 2 * sQK, pvT);
    }

    // 4) Scores: P[b] = scale * q[b] @ k[b]^T  (fp32 out)
    {
        dim3 grid(SEQ / 128, SEQ / 128, BATCH);
        hgemm_nt<false><<<grid, 256>>>(
            pqkv, pqkv + sQK, pP, LOWD, LOWD, LOWD, SEQ,
            sBS, sBS, (long long)SEQ * SEQ, scale);
    }

    // 5) Softmax: fp32 scores -> fp16 probs
    softmax_h<<<BATCH * SEQ, 256>>>(pP, pPh);

    // 6) AV: out[b] = Ph[b] @ vT[b]^T  (fp32 out)
    {
        dim3 grid(LOWD / 128, SEQ / 128, BATCH);
        hgemm_nt<false><<<grid, 256>>>(
            pPh, pvT, out, SEQ, SEQ, SEQ, LOWD,
            (long long)SEQ * SEQ, sBS, sBS, 1.0f);
    }
}